// round 9
// baseline (speedup 1.0000x reference)
#include <cuda_runtime.h>
#include <math.h>

#define BATCH 16
#define CH    128
#define NPIX  4096
#define M3    384
#define NHEAD 4
#define HDIM  32
#define SCALE 0.17677669529663687f   // 1/sqrt(32)
#define EPSV  1e-5f
#define NCHUNK 32                     // k_context chunks (4096/128)

// ---------------- scratch (device globals) ----------------
__device__ float g_qkv[BATCH * M3 * NPIX];            // q_softmax | exp(k) | v
__device__ float g_pre[BATCH * CH * NPIX];            // pre-norm output
__device__ float g_skvp[NCHUNK * BATCH * NHEAD * HDIM * HDIM]; // partial sum exp(k)*v
__device__ float g_skp [NCHUNK * BATCH * NHEAD * HDIM];        // partial sum exp(k)
__device__ float g_ctx[BATCH * NHEAD * HDIM * HDIM];  // reduced ctx = skv/sk
__device__ float g_M  [BATCH * CH * CH];              // w_out @ blockdiag(ctx^T)
__device__ float g_stats[BATCH * 2];                  // per-batch sum, sumsq

// ---------------- helpers ----------------
__device__ __forceinline__ unsigned f2tf(float x) {
    unsigned u;
    asm("cvt.rna.tf32.f32 %0, %1;" : "=r"(u) : "f"(x));
    return u;
}
__device__ __forceinline__ void mma_tf32(float* c, const unsigned* a, const unsigned* b) {
    asm volatile("mma.sync.aligned.m16n8k8.row.col.f32.tf32.tf32.f32 "
                 "{%0,%1,%2,%3}, {%4,%5,%6,%7}, {%8,%9}, {%0,%1,%2,%3};"
                 : "+f"(c[0]), "+f"(c[1]), "+f"(c[2]), "+f"(c[3])
                 : "r"(a[0]), "r"(a[1]), "r"(a[2]), "r"(a[3]),
                   "r"(b[0]), "r"(b[1]));
}

// ---------------- K0: zero stats ----------------
__global__ void k_zero() {
    if (threadIdx.x < BATCH * 2) g_stats[threadIdx.x] = 0.f;
}

// ============ K1: fused qkv GEMM (pipelined A staging) ============
#define BS_STRIDE 136
#define AS_STRIDE 36
#define AS_SIZE   (128 * AS_STRIDE)
#define SMEM_GEMM ((128 * BS_STRIDE + 2 * AS_SIZE) * 4)

__global__ void __launch_bounds__(256) k_gemm_fused(const float* __restrict__ W,
                                                    const float* __restrict__ X) {
    extern __shared__ unsigned smem_u[];
    unsigned* Bs  = smem_u;                          // [k][n] stride 136, full K
    unsigned* As0 = smem_u + 128 * BS_STRIDE;        // double-buffered A chunk
    const int b    = blockIdx.y;
    const int n0   = blockIdx.x * 128;
    const int tid  = threadIdx.x;
    const int lane = tid & 31;
    const int warp = tid >> 5;
    const int wm = warp >> 2, wn = warp & 3;         // 2x4 warps -> 64x32 each
    const float* Xb = X + (size_t)b * CH * NPIX;

    #pragma unroll
    for (int l = 0; l < 16; l++) {
        int t = tid + l * 256;
        int k = t >> 5, n4 = (t & 31) * 4;
        float4 v = *reinterpret_cast<const float4*>(&Xb[(size_t)k * NPIX + n0 + n4]);
        unsigned* s = &Bs[k * BS_STRIDE + n4];
        s[0] = f2tf(v.x); s[1] = f2tf(v.y); s[2] = f2tf(v.z); s[3] = f2tf(v.w);
    }

    // A staging indices (per thread): 4 rows x one 4-col group
    const int ar = tid >> 3;              // row within 128 (x4 loads)
    const int ak = (tid & 7) * 4;         // k4 within 32
    float* out = g_qkv + (size_t)b * M3 * NPIX;

    // preload mblk 0 chunk 0
    float4 pre[4];
    #pragma unroll
    for (int l = 0; l < 4; l++)
        pre[l] = *reinterpret_cast<const float4*>(&W[(size_t)(ar + l * 32) * CH + ak]);

    for (int mblk = 0; mblk < 3; mblk++) {
        const int m0 = mblk * 128;
        float acc[4][4][4];
        #pragma unroll
        for (int mt = 0; mt < 4; mt++)
            #pragma unroll
            for (int nt = 0; nt < 4; nt++)
                #pragma unroll
                for (int r = 0; r < 4; r++) acc[mt][nt][r] = 0.f;

        // store chunk 0
        {
            unsigned* As = As0;
            #pragma unroll
            for (int l = 0; l < 4; l++) {
                unsigned* s = &As[(ar + l * 32) * AS_STRIDE + ak];
                s[0] = f2tf(pre[l].x); s[1] = f2tf(pre[l].y);
                s[2] = f2tf(pre[l].z); s[3] = f2tf(pre[l].w);
            }
        }
        __syncthreads();

        #pragma unroll
        for (int ks = 0; ks < 4; ks++) {
            const int k0 = ks * 32;
            // issue next-chunk global loads early (overlap with mma)
            if (ks < 3) {
                #pragma unroll
                for (int l = 0; l < 4; l++)
                    pre[l] = *reinterpret_cast<const float4*>(
                        &W[(size_t)(m0 + ar + l * 32) * CH + (k0 + 32) + ak]);
            } else if (mblk < 2) {
                #pragma unroll
                for (int l = 0; l < 4; l++)
                    pre[l] = *reinterpret_cast<const float4*>(
                        &W[(size_t)((mblk + 1) * 128 + ar + l * 32) * CH + ak]);
            }

            unsigned* As = As0 + (ks & 1) * AS_SIZE;
            #pragma unroll
            for (int kk = 0; kk < 32; kk += 8) {
                unsigned a[4][4], bf[4][2];
                #pragma unroll
                for (int mt = 0; mt < 4; mt++) {
                    int r0 = wm * 64 + mt * 16 + (lane >> 2);
                    int c0 = kk + (lane & 3);
                    a[mt][0] = As[r0 * AS_STRIDE + c0];
                    a[mt][1] = As[(r0 + 8) * AS_STRIDE + c0];
                    a[mt][2] = As[r0 * AS_STRIDE + c0 + 4];
                    a[mt][3] = As[(r0 + 8) * AS_STRIDE + c0 + 4];
                }
                #pragma unroll
                for (int nt = 0; nt < 4; nt++) {
                    int cc = wn * 32 + nt * 8 + (lane >> 2);
                    int rr = k0 + kk + (lane & 3);
                    bf[nt][0] = Bs[rr * BS_STRIDE + cc];
                    bf[nt][1] = Bs[(rr + 4) * BS_STRIDE + cc];
                }
                #pragma unroll
                for (int mt = 0; mt < 4; mt++)
                    #pragma unroll
                    for (int nt = 0; nt < 4; nt++)
                        mma_tf32(acc[mt][nt], a[mt], bf[nt]);
            }

            if (ks < 3) {
                unsigned* Anext = As0 + ((ks + 1) & 1) * AS_SIZE;
                #pragma unroll
                for (int l = 0; l < 4; l++) {
                    unsigned* s = &Anext[(ar + l * 32) * AS_STRIDE + ak];
                    s[0] = f2tf(pre[l].x); s[1] = f2tf(pre[l].y);
                    s[2] = f2tf(pre[l].z); s[3] = f2tf(pre[l].w);
                }
                __syncthreads();
            }
        }
        __syncthreads();   // all mma done before As0 reuse next mblk

        if (mblk == 0) {
            // in-register q softmax over d per column (butterfly over lane bits 2..4)
            #pragma unroll
            for (int g = 0; g < 2; g++)
                #pragma unroll
                for (int nt = 0; nt < 4; nt++)
                    #pragma unroll
                    for (int c = 0; c < 2; c++) {
                        float v0 = acc[2 * g][nt][c],     v1 = acc[2 * g][nt][c + 2];
                        float v2 = acc[2 * g + 1][nt][c], v3 = acc[2 * g + 1][nt][c + 2];
                        float mx = fmaxf(fmaxf(v0, v1), fmaxf(v2, v3));
                        mx = fmaxf(mx, __shfl_xor_sync(0xffffffffu, mx, 4));
                        mx = fmaxf(mx, __shfl_xor_sync(0xffffffffu, mx, 8));
                        mx = fmaxf(mx, __shfl_xor_sync(0xffffffffu, mx, 16));
                        v0 = expf(v0 - mx); v1 = expf(v1 - mx);
                        v2 = expf(v2 - mx); v3 = expf(v3 - mx);
                        float s = v0 + v1 + v2 + v3;
                        s += __shfl_xor_sync(0xffffffffu, s, 4);
                        s += __shfl_xor_sync(0xffffffffu, s, 8);
                        s += __shfl_xor_sync(0xffffffffu, s, 16);
                        float inv = SCALE / s;
                        acc[2 * g][nt][c] = v0 * inv;     acc[2 * g][nt][c + 2] = v1 * inv;
                        acc[2 * g + 1][nt][c] = v2 * inv; acc[2 * g + 1][nt][c + 2] = v3 * inv;
                    }
        }

        const bool isK = (mblk == 1);
        #pragma unroll
        for (int mt = 0; mt < 4; mt++) {
            int row = m0 + wm * 64 + mt * 16 + (lane >> 2);
            #pragma unroll
            for (int nt = 0; nt < 4; nt++) {
                int col = n0 + wn * 32 + nt * 8 + (lane & 3) * 2;
                float2 v0 = make_float2(acc[mt][nt][0], acc[mt][nt][1]);
                float2 v1 = make_float2(acc[mt][nt][2], acc[mt][nt][3]);
                if (isK) { v0.x = expf(v0.x); v0.y = expf(v0.y);
                           v1.x = expf(v1.x); v1.y = expf(v1.y); }
                *reinterpret_cast<float2*>(&out[(size_t)row * NPIX + col])       = v0;
                *reinterpret_cast<float2*>(&out[(size_t)(row + 8) * NPIX + col]) = v1;
            }
        }
    }
}

// ---------------- K3: per-chunk partials of S_kv, S_k ----------------
#define SSTRIDE 260
__global__ void __launch_bounds__(256) k_context() {
    __shared__ float S[32 * SSTRIDE];
    const int chunk = blockIdx.x;
    const int b     = blockIdx.y;
    const int tid   = threadIdx.x;
    const int h     = tid >> 6;
    const int local = tid & 63;
    const int d0 = (local >> 3) << 2;
    const int e0 = (local & 7) << 2;

    float acc[4][4];
    float ksum[4] = {0.f, 0.f, 0.f, 0.f};
    #pragma unroll
    for (int i = 0; i < 4; i++)
        #pragma unroll
        for (int j = 0; j < 4; j++) acc[i][j] = 0.f;

    for (int sub = 0; sub < 4; sub++) {
        int c0 = chunk * 128 + sub * 32;
        #pragma unroll
        for (int l = 0; l < 8; l++) {
            int t = tid + l * 256;
            int r = t >> 3, c4 = (t & 7) * 4;
            float4 v = *reinterpret_cast<const float4*>(
                &g_qkv[((size_t)b * M3 + 128 + r) * NPIX + c0 + c4]);
            S[(c4 + 0) * SSTRIDE + r] = v.x;
            S[(c4 + 1) * SSTRIDE + r] = v.y;
            S[(c4 + 2) * SSTRIDE + r] = v.z;
            S[(c4 + 3) * SSTRIDE + r] = v.w;
        }
        __syncthreads();
        #pragma unroll 8
        for (int c = 0; c < 32; c++) {
            float4 ek = *reinterpret_cast<const float4*>(&S[c * SSTRIDE + h * HDIM + d0]);
            float4 vv = *reinterpret_cast<const float4*>(&S[c * SSTRIDE + 128 + h * HDIM + e0]);
            const float ekf[4] = {ek.x, ek.y, ek.z, ek.w};
            const float vvf[4] = {vv.x, vv.y, vv.z, vv.w};
            #pragma unroll
            for (int i = 0; i < 4; i++)
                #pragma unroll
                for (int j = 0; j < 4; j++)
                    acc[i][j] = fmaf(ekf[i], vvf[j], acc[i][j]);
            if ((local & 7) == 0) {
                #pragma unroll
                for (int i = 0; i < 4; i++) ksum[i] += ekf[i];
            }
        }
        __syncthreads();
    }
    size_t pbase = (((size_t)chunk * BATCH + b) * NHEAD + h) * (HDIM * HDIM);
    #pragma unroll
    for (int i = 0; i < 4; i++)
        *reinterpret_cast<float4*>(&g_skvp[pbase + (d0 + i) * HDIM + e0]) =
            make_float4(acc[i][0], acc[i][1], acc[i][2], acc[i][3]);
    if ((local & 7) == 0) {
        size_t kb = (((size_t)chunk * BATCH + b) * NHEAD + h) * HDIM;
        #pragma unroll
        for (int i = 0; i < 4; i++) g_skp[kb + d0 + i] = ksum[i];
    }
}

// ---------------- K3b: parallel reduce of partials -> ctx ----------------
// grid (4, NHEAD, BATCH): each thread reduces ONE ctx element over NCHUNK.
__global__ void __launch_bounds__(256) k_reduce2() {
    __shared__ float sk[HDIM];
    const int q = blockIdx.x;
    const int h = blockIdx.y;
    const int b = blockIdx.z;
    const int tid = threadIdx.x;
    const size_t stride_skv = (size_t)BATCH * NHEAD * HDIM * HDIM;
    const size_t stride_sk  = (size_t)BATCH * NHEAD * HDIM;
    const size_t base_skv = ((size_t)b * NHEAD + h) * (HDIM * HDIM);
    const size_t base_sk  = ((size_t)b * NHEAD + h) * HDIM;

    if (tid < HDIM) {
        float s = 0.f;
        #pragma unroll
        for (int c = 0; c < NCHUNK; c++)
            s += g_skp[base_sk + c * stride_sk + tid];
        sk[tid] = 1.f / s;
    }
    __syncthreads();

    int i = q * 256 + tid;
    float s = 0.f;
    #pragma unroll
    for (int c = 0; c < NCHUNK; c++)
        s += g_skvp[base_skv + c * stride_skv + i];
    g_ctx[base_skv + i] = s * sk[i >> 5];
}

// ---------------- K3c: M_b = w_out @ blockdiag(ctx^T) ----------------
__global__ void __launch_bounds__(256) k_buildM2(const float* __restrict__ Wout) {
    __shared__ float ctx[NHEAD * HDIM * HDIM];   // 4096 floats = 16 KB
    const int cblk = blockIdx.x;                 // 0..7 -> c rows [cblk*16, +16)
    const int b    = blockIdx.y;
    const int tid  = threadIdx.x;

    #pragma unroll
    for (int l = 0; l < 16; l++) {
        int i = tid + l * 256;
        ctx[i] = g_ctx[(size_t)b * (NHEAD * HDIM * HDIM) + i];
    }
    __syncthreads();

    #pragma unroll
    for (int l = 0; l < 8; l++) {
        int i = tid + l * 256;
        int c  = cblk * 16 + (i >> 7);
        int dg = i & 127;
        int h = dg >> 5, d = dg & 31;
        const float* wrow = Wout + (size_t)c * CH + h * HDIM;
        const float* cr   = ctx + (h * HDIM + d) * HDIM;
        float acc = 0.f;
        #pragma unroll
        for (int e = 0; e < HDIM; e++) acc = fmaf(wrow[e], cr[e], acc);
        g_M[(size_t)b * CH * CH + (size_t)c * CH + dg] = acc;
    }
}

// ---------------- K4: pre = M_b @ q_sm + bias ; stats (tf32 mma, pipelined) ----------------
#define PW_STRIDE 132
#define PB_SIZE   (32 * BS_STRIDE)
#define SMEM_PROJ ((128 * PW_STRIDE + 2 * PB_SIZE) * 4 + 64)

__global__ void __launch_bounds__(256) k_proj(const float* __restrict__ Bias) {
    extern __shared__ unsigned psmem[];
    unsigned* Ws  = psmem;                           // full 128x128 W, stride 132
    unsigned* Bs0 = psmem + 128 * PW_STRIDE;         // double-buffered q chunk
    __shared__ float s1[8], s2[8];
    const int b   = blockIdx.y;
    const int n0  = blockIdx.x * 128;
    const int tid = threadIdx.x;
    const int lane = tid & 31;
    const int warp = tid >> 5;
    const int wm = warp >> 2, wn = warp & 3;
    const float* W  = g_M + (size_t)b * CH * CH;
    const float* Qb = g_qkv + (size_t)b * M3 * NPIX;

    // load full W tile once: 4096 float4 / 256 threads = 16 each
    #pragma unroll
    for (int l = 0; l < 16; l++) {
        int t = tid + l * 256;
        int m = t >> 5, k4 = (t & 31) * 4;
        float4 v = *reinterpret_cast<const float4*>(&W[(size_t)m * CH + k4]);
        unsigned* s = &Ws[m * PW_STRIDE + k4];
        s[0] = f2tf(v.x); s[1] = f2tf(v.y); s[2] = f2tf(v.z); s[3] = f2tf(v.w);
    }

    // B staging: 32(k) x 128(n) per chunk = 1024 float4 -> 4 per thread
    const int br = tid >> 5;              // base k row (rows br + l*8)
    const int bn = (tid & 31) * 4;        // column group
    float4 bpre[4];
    #pragma unroll
    for (int l = 0; l < 4; l++)
        bpre[l] = *reinterpret_cast<const float4*>(
            &Qb[(size_t)(br + l * 8) * NPIX + n0 + bn]);
    #pragma unroll
    for (int l = 0; l < 4; l++) {
        unsigned* s = &Bs0[(br + l * 8) * BS_STRIDE + bn];
        s[0] = f2tf(bpre[l].x); s[1] = f2tf(bpre[l].y);
        s[2] = f2tf(bpre[l].z); s[3] = f2tf(bpre[l].w);
    }
    __syncthreads();

    float acc[4][4][4];
    #pragma unroll
    for (int mt = 0; mt < 4; mt++)
        #pragma unroll
        for (int nt = 0; nt < 4; nt++)
            #pragma unroll
            for (int r = 0; r < 4; r++) acc[mt][nt][r] = 0.f;

    #pragma unroll
    for (int ks = 0; ks < 4; ks++) {
        const int k0 = ks * 32;
        if (ks < 3) {
            #pragma unroll
            for (int l = 0; l < 4; l++)
                bpre[l] = *reinterpret_cast<const float4*>(
                    &Qb[(size_t)(k0 + 32 + br + l * 8) * NPIX + n0 + bn]);
        }

        unsigned* Bs = Bs0 + (ks & 1) * PB_SIZE;
        #pragma unroll
        for (int kk = 0; kk < 32; kk += 8) {
            unsigned a[4][4], bf[4][2];
            #pragma unroll
            for (int mt = 0; mt < 4; mt++) {
                int r0 = wm * 64 + mt * 16 + (lane >> 2);
                int c0 = k0 + kk + (lane & 3);
                a[mt][0] = Ws[r0 * PW_STRIDE + c0];
                a[mt][1] = Ws[(r0 + 8) * PW_STRIDE + c0];
                a[mt][2] = Ws[r0 * PW_STRIDE + c0 + 4];
                a[mt][3] = Ws[(r0 + 8) * PW_STRIDE + c0 + 4];
            }
            #pragma unroll
            for (int nt = 0; nt < 4; nt++) {
                int cc = wn * 32 + nt * 8 + (lane >> 2);
                int rr = kk + (lane & 3);
                bf[nt][0] = Bs[rr * BS_STRIDE + cc];
                bf[nt][1] = Bs[(rr + 4) * BS_STRIDE + cc];
            }
            #pragma unroll
            for (int mt = 0; mt < 4; mt++)
                #pragma unroll
                for (int nt = 0; nt < 4; nt++)
                    mma_tf32(acc[mt][nt], a[mt], bf[nt]);
        }

        if (ks < 3) {
            unsigned* Bn = Bs0 + ((ks + 1) & 1) * PB_SIZE;
            #pragma unroll
            for (int l = 0; l < 4; l++) {
                unsigned* s = &Bn[(br + l * 8) * BS_STRIDE + bn];
                s[0] = f2tf(bpre[l].x); s[1] = f2tf(bpre[l].y);
                s[2] = f2tf(bpre[l].z); s[3] = f2tf(bpre[l].w);
            }
            __syncthreads();
        }
    }

    float* out = g_pre + (size_t)b * CH * NPIX;
    float lsum = 0.f, lsq = 0.f;
    #pragma unroll
    for (int mt = 0; mt < 4; mt++) {
        int row = wm * 64 + mt * 16 + (lane >> 2);
        float bias0 = __ldg(&Bias[row]);
        float bias1 = __ldg(&Bias[row + 8]);
        #pragma unroll
        for (int nt = 0; nt < 4; nt++) {
            int col = n0 + wn * 32 + nt * 8 + (lane & 3) * 2;
            float2 v0 = make_float2(acc[mt][nt][0] + bias0, acc[mt][nt][1] + bias0);
            float2 v1 = make_float2(acc[mt][nt][2] + bias1, acc[mt][nt][3] + bias1);
            lsum += v0.x + v0.y + v1.x + v1.y;
            lsq = fmaf(v0.x, v0.x, lsq); lsq = fmaf(v0.y, v0.y, lsq);
            lsq = fmaf(v1.x, v1.x, lsq); lsq = fmaf(v1.y, v1.y, lsq);
            *reinterpret_cast<float2*>(&out[(size_t)row * NPIX + col])       = v0;
            *reinterpret_cast<float2*>(&out[(size_t)(row + 8) * NPIX + col]) = v1;
        }
    }
    #pragma unroll
    for (int off = 16; off > 0; off >>= 1) {
        lsum += __shfl_down_sync(0xffffffffu, lsum, off);
        lsq  += __shfl_down_sync(0xffffffffu, lsq,  off);
    }
    if (lane == 0) { s1[warp] = lsum; s2[warp] = lsq; }
    __syncthreads();
    if (tid == 0) {
        float t1 = 0.f, t2 = 0.f;
        #pragma unroll
        for (int w = 0; w < 8; w++) { t1 += s1[w]; t2 += s2[w]; }
        atomicAdd(&g_stats[b * 2 + 0], t1);
        atomicAdd(&g_stats[b * 2 + 1], t2);
    }
}

// ---------------- K5: LayerNorm normalize + affine ----------------
__global__ void k_norm(const float* __restrict__ gnw, const float* __restrict__ gnb,
                       float* __restrict__ out) {
    size_t i4 = (size_t)blockIdx.x * 256 + threadIdx.x;
    size_t idx = i4 * 4;
    const float invCN = 1.f / (float)(CH * NPIX);
    int b = (int)(idx / ((size_t)CH * NPIX));
    int c = (int)((idx / NPIX) & (CH - 1));
    float mean = g_stats[b * 2 + 0] * invCN;
    float var  = g_stats[b * 2 + 1] * invCN - mean * mean;
    float rstd = rsqrtf(var + EPSV);
    float w  = gnw[c] * rstd;
    float bb = gnb[c] - mean * w;
    float4 v = *reinterpret_cast<const float4*>(g_pre + idx);
    v.x = fmaf(v.x, w, bb);
    v.y = fmaf(v.y, w, bb);
    v.z = fmaf(v.z, w, bb);
    v.w = fmaf(v.w, w, bb);
    *reinterpret_cast<float4*>(out + idx) = v;
}

// ---------------- launcher ----------------
extern "C" void kernel_launch(void* const* d_in, const int* in_sizes, int n_in,
                              void* d_out, int out_size) {
    const float* x     = (const float*)d_in[0];
    const float* w_qkv = (const float*)d_in[1];
    const float* w_out = (const float*)d_in[2];
    const float* b_out = (const float*)d_in[3];
    const float* gnw   = (const float*)d_in[4];
    const float* gnb   = (const float*)d_in[5];

    cudaFuncSetAttribute(k_gemm_fused, cudaFuncAttributeMaxDynamicSharedMemorySize, SMEM_GEMM);
    cudaFuncSetAttribute(k_proj,       cudaFuncAttributeMaxDynamicSharedMemorySize, SMEM_PROJ);

    k_zero<<<1, 32>>>();
    k_gemm_fused<<<dim3(32, 16), 256, SMEM_GEMM>>>(w_qkv, x);
    k_context<<<dim3(NCHUNK, 16), 256>>>();
    k_reduce2<<<dim3(4, NHEAD, BATCH), 256>>>();
    k_buildM2<<<dim3(8, BATCH), 256>>>(w_out);
    k_proj<<<dim3(32, 16), 256, SMEM_PROJ>>>(b_out);
    k_norm<<<8192, 256>>>(gnw, gnb, (float*)d_out);
}

// round 10
// speedup vs baseline: 1.1431x; 1.1431x over previous
#include <cuda_runtime.h>
#include <math.h>

#define BATCH 16
#define CH    128
#define NPIX  4096
#define M3    384
#define NHEAD 4
#define HDIM  32
#define SCALE 0.17677669529663687f   // 1/sqrt(32)
#define EPSV  1e-5f
#define NCHUNK 32                     // k_context chunks (4096/128)

// ---------------- scratch (device globals) ----------------
__device__ float g_qkv[BATCH * M3 * NPIX];            // q_softmax | exp(k) | v
__device__ float g_pre[BATCH * CH * NPIX];            // pre-norm output
__device__ float g_skvp[NCHUNK * BATCH * NHEAD * HDIM * HDIM]; // partial sum exp(k)*v
__device__ float g_skp [NCHUNK * BATCH * NHEAD * HDIM];        // partial sum exp(k)
__device__ float g_ctx[BATCH * NHEAD * HDIM * HDIM];  // reduced ctx = skv/sk
__device__ float g_M  [BATCH * CH * CH];              // w_out @ blockdiag(ctx^T)
__device__ float g_stats[BATCH * 2];                  // per-batch sum, sumsq

// ---------------- helpers ----------------
__device__ __forceinline__ unsigned f2tf(float x) {
    unsigned u;
    asm("cvt.rna.tf32.f32 %0, %1;" : "=r"(u) : "f"(x));
    return u;
}
__device__ __forceinline__ void mma_tf32(float* c, const unsigned* a, const unsigned* b) {
    asm volatile("mma.sync.aligned.m16n8k8.row.col.f32.tf32.tf32.f32 "
                 "{%0,%1,%2,%3}, {%4,%5,%6,%7}, {%8,%9}, {%0,%1,%2,%3};"
                 : "+f"(c[0]), "+f"(c[1]), "+f"(c[2]), "+f"(c[3])
                 : "r"(a[0]), "r"(a[1]), "r"(a[2]), "r"(a[3]),
                   "r"(b[0]), "r"(b[1]));
}

// ============ K1: fused qkv GEMM (round-5 structure: B resident, simple A chunks) ============
#define BS_STRIDE 136
#define AS_STRIDE 36
#define SMEM_GEMM ((128 * BS_STRIDE + 128 * AS_STRIDE) * 4)

__global__ void __launch_bounds__(256) k_gemm_fused(const float* __restrict__ W,
                                                    const float* __restrict__ X) {
    extern __shared__ unsigned smem_u[];
    unsigned* Bs = smem_u;                       // [k][n] stride 136, full K
    unsigned* As = smem_u + 128 * BS_STRIDE;     // [m][k0..k0+31] stride 36
    const int b    = blockIdx.y;
    const int n0   = blockIdx.x * 128;
    const int tid  = threadIdx.x;
    const int lane = tid & 31;
    const int warp = tid >> 5;
    const int wm = warp >> 2, wn = warp & 3;     // 2x4 warps -> 64x32 each
    const float* Xb = X + (size_t)b * CH * NPIX;

    #pragma unroll
    for (int l = 0; l < 16; l++) {
        int t = tid + l * 256;
        int k = t >> 5, n4 = (t & 31) * 4;
        float4 v = *reinterpret_cast<const float4*>(&Xb[(size_t)k * NPIX + n0 + n4]);
        unsigned* s = &Bs[k * BS_STRIDE + n4];
        s[0] = f2tf(v.x); s[1] = f2tf(v.y); s[2] = f2tf(v.z); s[3] = f2tf(v.w);
    }
    __syncthreads();

    float* out = g_qkv + (size_t)b * M3 * NPIX;

    for (int mblk = 0; mblk < 3; mblk++) {
        const int m0 = mblk * 128;
        float acc[4][4][4];
        #pragma unroll
        for (int mt = 0; mt < 4; mt++)
            #pragma unroll
            for (int nt = 0; nt < 4; nt++)
                #pragma unroll
                for (int r = 0; r < 4; r++) acc[mt][nt][r] = 0.f;

        for (int k0 = 0; k0 < CH; k0 += 32) {
            #pragma unroll
            for (int l = 0; l < 4; l++) {        // A chunk: 128 x 32
                int t = tid + l * 256;
                int m = t >> 3, k4 = (t & 7) * 4;
                float4 v = *reinterpret_cast<const float4*>(&W[(size_t)(m0 + m) * CH + k0 + k4]);
                unsigned* s = &As[m * AS_STRIDE + k4];
                s[0] = f2tf(v.x); s[1] = f2tf(v.y); s[2] = f2tf(v.z); s[3] = f2tf(v.w);
            }
            __syncthreads();
            #pragma unroll
            for (int kk = 0; kk < 32; kk += 8) {
                unsigned a[4][4], bf[4][2];
                #pragma unroll
                for (int mt = 0; mt < 4; mt++) {
                    int r0 = wm * 64 + mt * 16 + (lane >> 2);
                    int c0 = kk + (lane & 3);
                    a[mt][0] = As[r0 * AS_STRIDE + c0];
                    a[mt][1] = As[(r0 + 8) * AS_STRIDE + c0];
                    a[mt][2] = As[r0 * AS_STRIDE + c0 + 4];
                    a[mt][3] = As[(r0 + 8) * AS_STRIDE + c0 + 4];
                }
                #pragma unroll
                for (int nt = 0; nt < 4; nt++) {
                    int cc = wn * 32 + nt * 8 + (lane >> 2);
                    int rr = k0 + kk + (lane & 3);
                    bf[nt][0] = Bs[rr * BS_STRIDE + cc];
                    bf[nt][1] = Bs[(rr + 4) * BS_STRIDE + cc];
                }
                #pragma unroll
                for (int mt = 0; mt < 4; mt++)
                    #pragma unroll
                    for (int nt = 0; nt < 4; nt++)
                        mma_tf32(acc[mt][nt], a[mt], bf[nt]);
            }
            __syncthreads();
        }

        if (mblk == 0) {
            // in-register q softmax over d per column (butterfly over lane bits 2..4)
            #pragma unroll
            for (int g = 0; g < 2; g++)
                #pragma unroll
                for (int nt = 0; nt < 4; nt++)
                    #pragma unroll
                    for (int c = 0; c < 2; c++) {
                        float v0 = acc[2 * g][nt][c],     v1 = acc[2 * g][nt][c + 2];
                        float v2 = acc[2 * g + 1][nt][c], v3 = acc[2 * g + 1][nt][c + 2];
                        float mx = fmaxf(fmaxf(v0, v1), fmaxf(v2, v3));
                        mx = fmaxf(mx, __shfl_xor_sync(0xffffffffu, mx, 4));
                        mx = fmaxf(mx, __shfl_xor_sync(0xffffffffu, mx, 8));
                        mx = fmaxf(mx, __shfl_xor_sync(0xffffffffu, mx, 16));
                        v0 = expf(v0 - mx); v1 = expf(v1 - mx);
                        v2 = expf(v2 - mx); v3 = expf(v3 - mx);
                        float s = v0 + v1 + v2 + v3;
                        s += __shfl_xor_sync(0xffffffffu, s, 4);
                        s += __shfl_xor_sync(0xffffffffu, s, 8);
                        s += __shfl_xor_sync(0xffffffffu, s, 16);
                        float inv = SCALE / s;
                        acc[2 * g][nt][c] = v0 * inv;     acc[2 * g][nt][c + 2] = v1 * inv;
                        acc[2 * g + 1][nt][c] = v2 * inv; acc[2 * g + 1][nt][c + 2] = v3 * inv;
                    }
        }

        const bool isK = (mblk == 1);
        #pragma unroll
        for (int mt = 0; mt < 4; mt++) {
            int row = m0 + wm * 64 + mt * 16 + (lane >> 2);
            #pragma unroll
            for (int nt = 0; nt < 4; nt++) {
                int col = n0 + wn * 32 + nt * 8 + (lane & 3) * 2;
                float2 v0 = make_float2(acc[mt][nt][0], acc[mt][nt][1]);
                float2 v1 = make_float2(acc[mt][nt][2], acc[mt][nt][3]);
                if (isK) { v0.x = expf(v0.x); v0.y = expf(v0.y);
                           v1.x = expf(v1.x); v1.y = expf(v1.y); }
                *reinterpret_cast<float2*>(&out[(size_t)row * NPIX + col])       = v0;
                *reinterpret_cast<float2*>(&out[(size_t)(row + 8) * NPIX + col]) = v1;
            }
        }
        __syncthreads();
    }
}

// ---------------- K3: per-chunk partials of S_kv, S_k ----------------
#define SSTRIDE 260
__global__ void __launch_bounds__(256) k_context() {
    __shared__ float S[32 * SSTRIDE];
    const int chunk = blockIdx.x;
    const int b     = blockIdx.y;
    const int tid   = threadIdx.x;
    const int h     = tid >> 6;
    const int local = tid & 63;
    const int d0 = (local >> 3) << 2;
    const int e0 = (local & 7) << 2;

    float acc[4][4];
    float ksum[4] = {0.f, 0.f, 0.f, 0.f};
    #pragma unroll
    for (int i = 0; i < 4; i++)
        #pragma unroll
        for (int j = 0; j < 4; j++) acc[i][j] = 0.f;

    for (int sub = 0; sub < 4; sub++) {
        int c0 = chunk * 128 + sub * 32;
        #pragma unroll
        for (int l = 0; l < 8; l++) {
            int t = tid + l * 256;
            int r = t >> 3, c4 = (t & 7) * 4;
            float4 v = *reinterpret_cast<const float4*>(
                &g_qkv[((size_t)b * M3 + 128 + r) * NPIX + c0 + c4]);
            S[(c4 + 0) * SSTRIDE + r] = v.x;
            S[(c4 + 1) * SSTRIDE + r] = v.y;
            S[(c4 + 2) * SSTRIDE + r] = v.z;
            S[(c4 + 3) * SSTRIDE + r] = v.w;
        }
        __syncthreads();
        #pragma unroll 8
        for (int c = 0; c < 32; c++) {
            float4 ek = *reinterpret_cast<const float4*>(&S[c * SSTRIDE + h * HDIM + d0]);
            float4 vv = *reinterpret_cast<const float4*>(&S[c * SSTRIDE + 128 + h * HDIM + e0]);
            const float ekf[4] = {ek.x, ek.y, ek.z, ek.w};
            const float vvf[4] = {vv.x, vv.y, vv.z, vv.w};
            #pragma unroll
            for (int i = 0; i < 4; i++)
                #pragma unroll
                for (int j = 0; j < 4; j++)
                    acc[i][j] = fmaf(ekf[i], vvf[j], acc[i][j]);
            if ((local & 7) == 0) {
                #pragma unroll
                for (int i = 0; i < 4; i++) ksum[i] += ekf[i];
            }
        }
        __syncthreads();
    }
    size_t pbase = (((size_t)chunk * BATCH + b) * NHEAD + h) * (HDIM * HDIM);
    #pragma unroll
    for (int i = 0; i < 4; i++)
        *reinterpret_cast<float4*>(&g_skvp[pbase + (d0 + i) * HDIM + e0]) =
            make_float4(acc[i][0], acc[i][1], acc[i][2], acc[i][3]);
    if ((local & 7) == 0) {
        size_t kb = (((size_t)chunk * BATCH + b) * NHEAD + h) * HDIM;
        #pragma unroll
        for (int i = 0; i < 4; i++) g_skp[kb + d0 + i] = ksum[i];
    }
}

// ---------------- K3b: parallel reduce of partials -> ctx (verified win) ----------------
// grid (4, NHEAD, BATCH): each thread reduces ONE ctx element over NCHUNK.
__global__ void __launch_bounds__(256) k_reduce2() {
    __shared__ float sk[HDIM];
    const int q = blockIdx.x;
    const int h = blockIdx.y;
    const int b = blockIdx.z;
    const int tid = threadIdx.x;
    const size_t stride_skv = (size_t)BATCH * NHEAD * HDIM * HDIM;
    const size_t stride_sk  = (size_t)BATCH * NHEAD * HDIM;
    const size_t base_skv = ((size_t)b * NHEAD + h) * (HDIM * HDIM);
    const size_t base_sk  = ((size_t)b * NHEAD + h) * HDIM;

    if (tid < HDIM) {
        float s = 0.f;
        #pragma unroll
        for (int c = 0; c < NCHUNK; c++)
            s += g_skp[base_sk + c * stride_sk + tid];
        sk[tid] = 1.f / s;
    }
    __syncthreads();

    int i = q * 256 + tid;
    float s = 0.f;
    #pragma unroll
    for (int c = 0; c < NCHUNK; c++)
        s += g_skvp[base_skv + c * stride_skv + i];
    g_ctx[base_skv + i] = s * sk[i >> 5];
}

// ---------------- K3c: M_b = w_out @ blockdiag(ctx^T); also zero stats ----------------
__global__ void __launch_bounds__(256) k_buildM2(const float* __restrict__ Wout) {
    __shared__ float ctx[NHEAD * HDIM * HDIM];   // 4096 floats = 16 KB
    const int cblk = blockIdx.x;                 // 0..7 -> c rows [cblk*16, +16)
    const int b    = blockIdx.y;
    const int tid  = threadIdx.x;

    // zero per-batch stats before k_proj's atomics (cblk 0 only)
    if (cblk == 0 && tid < 2) g_stats[b * 2 + tid] = 0.f;

    #pragma unroll
    for (int l = 0; l < 16; l++) {
        int i = tid + l * 256;
        ctx[i] = g_ctx[(size_t)b * (NHEAD * HDIM * HDIM) + i];
    }
    __syncthreads();

    #pragma unroll
    for (int l = 0; l < 8; l++) {
        int i = tid + l * 256;
        int c  = cblk * 16 + (i >> 7);
        int dg = i & 127;
        int h = dg >> 5, d = dg & 31;
        const float* wrow = Wout + (size_t)c * CH + h * HDIM;
        const float* cr   = ctx + (h * HDIM + d) * HDIM;
        float acc = 0.f;
        #pragma unroll
        for (int e = 0; e < HDIM; e++) acc = fmaf(wrow[e], cr[e], acc);
        g_M[(size_t)b * CH * CH + (size_t)c * CH + dg] = acc;
    }
}

// ---------------- K4: pre = M_b @ q_sm + bias ; stats (round-5 structure) ----------------
__global__ void __launch_bounds__(256) k_proj(const float* __restrict__ Bias) {
    __shared__ unsigned As[128 * 36];
    __shared__ unsigned Bs[32 * 136];
    __shared__ float s1[8], s2[8];
    const int b   = blockIdx.y;
    const int n0  = blockIdx.x * 128;
    const int tid = threadIdx.x;
    const int lane = tid & 31;
    const int warp = tid >> 5;
    const int wm = warp >> 2, wn = warp & 3;
    const float* W  = g_M + (size_t)b * CH * CH;
    const float* Qb = g_qkv + (size_t)b * M3 * NPIX;

    float acc[4][4][4];
    #pragma unroll
    for (int mt = 0; mt < 4; mt++)
        #pragma unroll
        for (int nt = 0; nt < 4; nt++)
            #pragma unroll
            for (int r = 0; r < 4; r++) acc[mt][nt][r] = 0.f;

    for (int k0 = 0; k0 < CH; k0 += 32) {
        #pragma unroll
        for (int l = 0; l < 4; l++) {
            int t = tid + l * 256;
            int m = t >> 3, k4 = (t & 7) * 4;
            float4 v = *reinterpret_cast<const float4*>(&W[(size_t)m * CH + k0 + k4]);
            As[m * 36 + k4 + 0] = f2tf(v.x);
            As[m * 36 + k4 + 1] = f2tf(v.y);
            As[m * 36 + k4 + 2] = f2tf(v.z);
            As[m * 36 + k4 + 3] = f2tf(v.w);
        }
        #pragma unroll
        for (int l = 0; l < 4; l++) {
            int t = tid + l * 256;
            int k = t >> 5, n4 = (t & 31) * 4;
            float4 v = *reinterpret_cast<const float4*>(&Qb[(size_t)(k0 + k) * NPIX + n0 + n4]);
            Bs[k * 136 + n4 + 0] = f2tf(v.x);
            Bs[k * 136 + n4 + 1] = f2tf(v.y);
            Bs[k * 136 + n4 + 2] = f2tf(v.z);
            Bs[k * 136 + n4 + 3] = f2tf(v.w);
        }
        __syncthreads();
        #pragma unroll
        for (int kk = 0; kk < 32; kk += 8) {
            unsigned a[4][4], bf[4][2];
            #pragma unroll
            for (int mt = 0; mt < 4; mt++) {
                int r0 = wm * 64 + mt * 16 + (lane >> 2);
                int c0 = kk + (lane & 3);
                a[mt][0] = As[r0 * 36 + c0];
                a[mt][1] = As[(r0 + 8) * 36 + c0];
                a[mt][2] = As[r0 * 36 + c0 + 4];
                a[mt][3] = As[(r0 + 8) * 36 + c0 + 4];
            }
            #pragma unroll
            for (int nt = 0; nt < 4; nt++) {
                int cc = wn * 32 + nt * 8 + (lane >> 2);
                int rr = kk + (lane & 3);
                bf[nt][0] = Bs[rr * 136 + cc];
                bf[nt][1] = Bs[(rr + 4) * 136 + cc];
            }
            #pragma unroll
            for (int mt = 0; mt < 4; mt++)
                #pragma unroll
                for (int nt = 0; nt < 4; nt++)
                    mma_tf32(acc[mt][nt], a[mt], bf[nt]);
        }
        __syncthreads();
    }

    float* out = g_pre + (size_t)b * CH * NPIX;
    float lsum = 0.f, lsq = 0.f;
    #pragma unroll
    for (int mt = 0; mt < 4; mt++) {
        int row = wm * 64 + mt * 16 + (lane >> 2);
        float bias0 = __ldg(&Bias[row]);
        float bias1 = __ldg(&Bias[row + 8]);
        #pragma unroll
        for (int nt = 0; nt < 4; nt++) {
            int col = n0 + wn * 32 + nt * 8 + (lane & 3) * 2;
            float2 v0 = make_float2(acc[mt][nt][0] + bias0, acc[mt][nt][1] + bias0);
            float2 v1 = make_float2(acc[mt][nt][2] + bias1, acc[mt][nt][3] + bias1);
            lsum += v0.x + v0.y + v1.x + v1.y;
            lsq = fmaf(v0.x, v0.x, lsq); lsq = fmaf(v0.y, v0.y, lsq);
            lsq = fmaf(v1.x, v1.x, lsq); lsq = fmaf(v1.y, v1.y, lsq);
            *reinterpret_cast<float2*>(&out[(size_t)row * NPIX + col])       = v0;
            *reinterpret_cast<float2*>(&out[(size_t)(row + 8) * NPIX + col]) = v1;
        }
    }
    #pragma unroll
    for (int off = 16; off > 0; off >>= 1) {
        lsum += __shfl_down_sync(0xffffffffu, lsum, off);
        lsq  += __shfl_down_sync(0xffffffffu, lsq,  off);
    }
    if (lane == 0) { s1[warp] = lsum; s2[warp] = lsq; }
    __syncthreads();
    if (tid == 0) {
        float t1 = 0.f, t2 = 0.f;
        #pragma unroll
        for (int w = 0; w < 8; w++) { t1 += s1[w]; t2 += s2[w]; }
        atomicAdd(&g_stats[b * 2 + 0], t1);
        atomicAdd(&g_stats[b * 2 + 1], t2);
    }
}

// ---------------- K5: LayerNorm normalize + affine ----------------
__global__ void k_norm(const float* __restrict__ gnw, const float* __restrict__ gnb,
                       float* __restrict__ out) {
    size_t i4 = (size_t)blockIdx.x * 256 + threadIdx.x;
    size_t idx = i4 * 4;
    const float invCN = 1.f / (float)(CH * NPIX);
    int b = (int)(idx / ((size_t)CH * NPIX));
    int c = (int)((idx / NPIX) & (CH - 1));
    float mean = g_stats[b * 2 + 0] * invCN;
    float var  = g_stats[b * 2 + 1] * invCN - mean * mean;
    float rstd = rsqrtf(var + EPSV);
    float w  = gnw[c] * rstd;
    float bb = gnb[c] - mean * w;
    float4 v = *reinterpret_cast<const float4*>(g_pre + idx);
    v.x = fmaf(v.x, w, bb);
    v.y = fmaf(v.y, w, bb);
    v.z = fmaf(v.z, w, bb);
    v.w = fmaf(v.w, w, bb);
    *reinterpret_cast<float4*>(out + idx) = v;
}

// ---------------- launcher ----------------
extern "C" void kernel_launch(void* const* d_in, const int* in_sizes, int n_in,
                              void* d_out, int out_size) {
    const float* x     = (const float*)d_in[0];
    const float* w_qkv = (const float*)d_in[1];
    const float* w_out = (const float*)d_in[2];
    const float* b_out = (const float*)d_in[3];
    const float* gnw   = (const float*)d_in[4];
    const float* gnb   = (const float*)d_in[5];

    cudaFuncSetAttribute(k_gemm_fused, cudaFuncAttributeMaxDynamicSharedMemorySize, SMEM_GEMM);

    k_gemm_fused<<<dim3(32, 16), 256, SMEM_GEMM>>>(w_qkv, x);
    k_context<<<dim3(NCHUNK, 16), 256>>>();
    k_reduce2<<<dim3(4, NHEAD, BATCH), 256>>>();
    k_buildM2<<<dim3(8, BATCH), 256>>>(w_out);
    k_proj<<<dim3(32, 16), 256>>>(b_out);
    k_norm<<<8192, 256>>>(gnw, gnb, (float*)d_out);
}

// round 11
// speedup vs baseline: 1.1651x; 1.0192x over previous
#include <cuda_runtime.h>
#include <math.h>

#define BATCH 16
#define CH    128
#define NPIX  4096
#define M3    384
#define NHEAD 4
#define HDIM  32
#define SCALE 0.17677669529663687f   // 1/sqrt(32)
#define EPSV  1e-5f
#define NCHUNK 32                     // k_context chunks (4096/128)

// ---------------- scratch (device globals) ----------------
__device__ float g_qkv[BATCH * M3 * NPIX];            // q_softmax | exp(k) | v
__device__ float g_pre[BATCH * CH * NPIX];            // pre-norm output
__device__ float g_skvp[NCHUNK * BATCH * NHEAD * HDIM * HDIM]; // partial sum exp(k)*v
__device__ float g_skp [NCHUNK * BATCH * NHEAD * HDIM];        // partial sum exp(k)
__device__ float g_ctx[BATCH * NHEAD * HDIM * HDIM];  // reduced ctx = skv/sk
__device__ float g_M  [BATCH * CH * CH];              // w_out @ blockdiag(ctx^T)
__device__ float g_stats[BATCH * 2];                  // per-batch sum, sumsq

// ---------------- helpers ----------------
__device__ __forceinline__ unsigned f2tf(float x) {
    unsigned u;
    asm("cvt.rna.tf32.f32 %0, %1;" : "=r"(u) : "f"(x));
    return u;
}
__device__ __forceinline__ void mma_tf32(float* c, const unsigned* a, const unsigned* b) {
    asm volatile("mma.sync.aligned.m16n8k8.row.col.f32.tf32.tf32.f32 "
                 "{%0,%1,%2,%3}, {%4,%5,%6,%7}, {%8,%9}, {%0,%1,%2,%3};"
                 : "+f"(c[0]), "+f"(c[1]), "+f"(c[2]), "+f"(c[3])
                 : "r"(a[0]), "r"(a[1]), "r"(a[2]), "r"(a[3]),
                   "r"(b[0]), "r"(b[1]));
}

// ============ K1: fused qkv GEMM (round-5 structure: B resident, simple A chunks) ============
#define BS_STRIDE 136
#define AS_STRIDE 36
#define SMEM_GEMM ((128 * BS_STRIDE + 128 * AS_STRIDE) * 4)

__global__ void __launch_bounds__(256) k_gemm_fused(const float* __restrict__ W,
                                                    const float* __restrict__ X) {
    extern __shared__ unsigned smem_u[];
    unsigned* Bs = smem_u;                       // [k][n] stride 136, full K
    unsigned* As = smem_u + 128 * BS_STRIDE;     // [m][k0..k0+31] stride 36
    const int b    = blockIdx.y;
    const int n0   = blockIdx.x * 128;
    const int tid  = threadIdx.x;
    const int lane = tid & 31;
    const int warp = tid >> 5;
    const int wm = warp >> 2, wn = warp & 3;     // 2x4 warps -> 64x32 each
    const float* Xb = X + (size_t)b * CH * NPIX;

    #pragma unroll
    for (int l = 0; l < 16; l++) {
        int t = tid + l * 256;
        int k = t >> 5, n4 = (t & 31) * 4;
        float4 v = *reinterpret_cast<const float4*>(&Xb[(size_t)k * NPIX + n0 + n4]);
        unsigned* s = &Bs[k * BS_STRIDE + n4];
        s[0] = f2tf(v.x); s[1] = f2tf(v.y); s[2] = f2tf(v.z); s[3] = f2tf(v.w);
    }
    __syncthreads();

    float* out = g_qkv + (size_t)b * M3 * NPIX;

    for (int mblk = 0; mblk < 3; mblk++) {
        const int m0 = mblk * 128;
        float acc[4][4][4];
        #pragma unroll
        for (int mt = 0; mt < 4; mt++)
            #pragma unroll
            for (int nt = 0; nt < 4; nt++)
                #pragma unroll
                for (int r = 0; r < 4; r++) acc[mt][nt][r] = 0.f;

        for (int k0 = 0; k0 < CH; k0 += 32) {
            #pragma unroll
            for (int l = 0; l < 4; l++) {        // A chunk: 128 x 32
                int t = tid + l * 256;
                int m = t >> 3, k4 = (t & 7) * 4;
                float4 v = *reinterpret_cast<const float4*>(&W[(size_t)(m0 + m) * CH + k0 + k4]);
                unsigned* s = &As[m * AS_STRIDE + k4];
                s[0] = f2tf(v.x); s[1] = f2tf(v.y); s[2] = f2tf(v.z); s[3] = f2tf(v.w);
            }
            __syncthreads();
            #pragma unroll
            for (int kk = 0; kk < 32; kk += 8) {
                unsigned a[4][4], bf[4][2];
                #pragma unroll
                for (int mt = 0; mt < 4; mt++) {
                    int r0 = wm * 64 + mt * 16 + (lane >> 2);
                    int c0 = kk + (lane & 3);
                    a[mt][0] = As[r0 * AS_STRIDE + c0];
                    a[mt][1] = As[(r0 + 8) * AS_STRIDE + c0];
                    a[mt][2] = As[r0 * AS_STRIDE + c0 + 4];
                    a[mt][3] = As[(r0 + 8) * AS_STRIDE + c0 + 4];
                }
                #pragma unroll
                for (int nt = 0; nt < 4; nt++) {
                    int cc = wn * 32 + nt * 8 + (lane >> 2);
                    int rr = k0 + kk + (lane & 3);
                    bf[nt][0] = Bs[rr * BS_STRIDE + cc];
                    bf[nt][1] = Bs[(rr + 4) * BS_STRIDE + cc];
                }
                #pragma unroll
                for (int mt = 0; mt < 4; mt++)
                    #pragma unroll
                    for (int nt = 0; nt < 4; nt++)
                        mma_tf32(acc[mt][nt], a[mt], bf[nt]);
            }
            __syncthreads();
        }

        if (mblk == 0) {
            // in-register q softmax over d per column (butterfly over lane bits 2..4)
            #pragma unroll
            for (int g = 0; g < 2; g++)
                #pragma unroll
                for (int nt = 0; nt < 4; nt++)
                    #pragma unroll
                    for (int c = 0; c < 2; c++) {
                        float v0 = acc[2 * g][nt][c],     v1 = acc[2 * g][nt][c + 2];
                        float v2 = acc[2 * g + 1][nt][c], v3 = acc[2 * g + 1][nt][c + 2];
                        float mx = fmaxf(fmaxf(v0, v1), fmaxf(v2, v3));
                        mx = fmaxf(mx, __shfl_xor_sync(0xffffffffu, mx, 4));
                        mx = fmaxf(mx, __shfl_xor_sync(0xffffffffu, mx, 8));
                        mx = fmaxf(mx, __shfl_xor_sync(0xffffffffu, mx, 16));
                        v0 = expf(v0 - mx); v1 = expf(v1 - mx);
                        v2 = expf(v2 - mx); v3 = expf(v3 - mx);
                        float s = v0 + v1 + v2 + v3;
                        s += __shfl_xor_sync(0xffffffffu, s, 4);
                        s += __shfl_xor_sync(0xffffffffu, s, 8);
                        s += __shfl_xor_sync(0xffffffffu, s, 16);
                        float inv = SCALE / s;
                        acc[2 * g][nt][c] = v0 * inv;     acc[2 * g][nt][c + 2] = v1 * inv;
                        acc[2 * g + 1][nt][c] = v2 * inv; acc[2 * g + 1][nt][c + 2] = v3 * inv;
                    }
        }

        const bool isK = (mblk == 1);
        #pragma unroll
        for (int mt = 0; mt < 4; mt++) {
            int row = m0 + wm * 64 + mt * 16 + (lane >> 2);
            #pragma unroll
            for (int nt = 0; nt < 4; nt++) {
                int col = n0 + wn * 32 + nt * 8 + (lane & 3) * 2;
                float2 v0 = make_float2(acc[mt][nt][0], acc[mt][nt][1]);
                float2 v1 = make_float2(acc[mt][nt][2], acc[mt][nt][3]);
                if (isK) { v0.x = expf(v0.x); v0.y = expf(v0.y);
                           v1.x = expf(v1.x); v1.y = expf(v1.y); }
                *reinterpret_cast<float2*>(&out[(size_t)row * NPIX + col])       = v0;
                *reinterpret_cast<float2*>(&out[(size_t)(row + 8) * NPIX + col]) = v1;
            }
        }
        __syncthreads();
    }
}

// ---------------- K3: per-chunk partials of S_kv, S_k ----------------
#define SSTRIDE 260
__global__ void __launch_bounds__(256) k_context() {
    __shared__ float S[32 * SSTRIDE];
    const int chunk = blockIdx.x;
    const int b     = blockIdx.y;
    const int tid   = threadIdx.x;
    const int h     = tid >> 6;
    const int local = tid & 63;
    const int d0 = (local >> 3) << 2;
    const int e0 = (local & 7) << 2;

    float acc[4][4];
    float ksum[4] = {0.f, 0.f, 0.f, 0.f};
    #pragma unroll
    for (int i = 0; i < 4; i++)
        #pragma unroll
        for (int j = 0; j < 4; j++) acc[i][j] = 0.f;

    for (int sub = 0; sub < 4; sub++) {
        int c0 = chunk * 128 + sub * 32;
        #pragma unroll
        for (int l = 0; l < 8; l++) {
            int t = tid + l * 256;
            int r = t >> 3, c4 = (t & 7) * 4;
            float4 v = *reinterpret_cast<const float4*>(
                &g_qkv[((size_t)b * M3 + 128 + r) * NPIX + c0 + c4]);
            S[(c4 + 0) * SSTRIDE + r] = v.x;
            S[(c4 + 1) * SSTRIDE + r] = v.y;
            S[(c4 + 2) * SSTRIDE + r] = v.z;
            S[(c4 + 3) * SSTRIDE + r] = v.w;
        }
        __syncthreads();
        #pragma unroll 8
        for (int c = 0; c < 32; c++) {
            float4 ek = *reinterpret_cast<const float4*>(&S[c * SSTRIDE + h * HDIM + d0]);
            float4 vv = *reinterpret_cast<const float4*>(&S[c * SSTRIDE + 128 + h * HDIM + e0]);
            const float ekf[4] = {ek.x, ek.y, ek.z, ek.w};
            const float vvf[4] = {vv.x, vv.y, vv.z, vv.w};
            #pragma unroll
            for (int i = 0; i < 4; i++)
                #pragma unroll
                for (int j = 0; j < 4; j++)
                    acc[i][j] = fmaf(ekf[i], vvf[j], acc[i][j]);
            if ((local & 7) == 0) {
                #pragma unroll
                for (int i = 0; i < 4; i++) ksum[i] += ekf[i];
            }
        }
        __syncthreads();
    }
    size_t pbase = (((size_t)chunk * BATCH + b) * NHEAD + h) * (HDIM * HDIM);
    #pragma unroll
    for (int i = 0; i < 4; i++)
        *reinterpret_cast<float4*>(&g_skvp[pbase + (d0 + i) * HDIM + e0]) =
            make_float4(acc[i][0], acc[i][1], acc[i][2], acc[i][3]);
    if ((local & 7) == 0) {
        size_t kb = (((size_t)chunk * BATCH + b) * NHEAD + h) * HDIM;
        #pragma unroll
        for (int i = 0; i < 4; i++) g_skp[kb + d0 + i] = ksum[i];
    }
}

// ---------------- K3b: parallel reduce of partials -> ctx (verified win) ----------------
__global__ void __launch_bounds__(256) k_reduce2() {
    __shared__ float sk[HDIM];
    const int q = blockIdx.x;
    const int h = blockIdx.y;
    const int b = blockIdx.z;
    const int tid = threadIdx.x;
    const size_t stride_skv = (size_t)BATCH * NHEAD * HDIM * HDIM;
    const size_t stride_sk  = (size_t)BATCH * NHEAD * HDIM;
    const size_t base_skv = ((size_t)b * NHEAD + h) * (HDIM * HDIM);
    const size_t base_sk  = ((size_t)b * NHEAD + h) * HDIM;

    if (tid < HDIM) {
        float s = 0.f;
        #pragma unroll
        for (int c = 0; c < NCHUNK; c++)
            s += g_skp[base_sk + c * stride_sk + tid];
        sk[tid] = 1.f / s;
    }
    __syncthreads();

    int i = q * 256 + tid;
    float s = 0.f;
    #pragma unroll
    for (int c = 0; c < NCHUNK; c++)
        s += g_skvp[base_skv + c * stride_skv + i];
    g_ctx[base_skv + i] = s * sk[i >> 5];
}

// ---------------- K3c: M_b = w_out @ blockdiag(ctx^T); register-resident, no smem ----------------
// grid (16, BATCH), 256 threads. Each thread: dg = tid&127 fixed -> ONE ctx row in regs;
// 4 outputs at c = cblk*8 + (tid>>7) + l*2. Warp-uniform Wout segments broadcast via L2.
__global__ void __launch_bounds__(256) k_buildM2(const float* __restrict__ Wout) {
    const int cblk = blockIdx.x;                 // 0..15 -> c rows [cblk*8, +8)
    const int b    = blockIdx.y;
    const int tid  = threadIdx.x;

    // zero per-batch stats before k_proj's atomics (one block per batch)
    if (cblk == 0 && tid < 2) g_stats[b * 2 + tid] = 0.f;

    const int dg = tid & 127;
    const int h  = dg >> 5, d = dg & 31;
    const int chalf = tid >> 7;                  // 0 or 1

    // load this thread's ctx row (32 floats) into registers
    const float* cr = g_ctx + ((size_t)b * NHEAD + h) * (HDIM * HDIM) + d * HDIM;
    float4 cv[8];
    #pragma unroll
    for (int e = 0; e < 8; e++) cv[e] = __ldg(reinterpret_cast<const float4*>(cr) + e);

    float* Mb = g_M + (size_t)b * CH * CH;
    #pragma unroll
    for (int l = 0; l < 4; l++) {
        int c = cblk * 8 + chalf + l * 2;
        const float4* wrow = reinterpret_cast<const float4*>(Wout + (size_t)c * CH + h * HDIM);
        float a0 = 0.f, a1 = 0.f, a2 = 0.f, a3 = 0.f;
        #pragma unroll
        for (int e = 0; e < 8; e += 4) {
            float4 w0 = __ldg(wrow + e),     w1 = __ldg(wrow + e + 1);
            float4 w2 = __ldg(wrow + e + 2), w3 = __ldg(wrow + e + 3);
            a0 = fmaf(w0.x, cv[e].x, a0);     a0 = fmaf(w0.y, cv[e].y, a0);
            a0 = fmaf(w0.z, cv[e].z, a0);     a0 = fmaf(w0.w, cv[e].w, a0);
            a1 = fmaf(w1.x, cv[e + 1].x, a1); a1 = fmaf(w1.y, cv[e + 1].y, a1);
            a1 = fmaf(w1.z, cv[e + 1].z, a1); a1 = fmaf(w1.w, cv[e + 1].w, a1);
            a2 = fmaf(w2.x, cv[e + 2].x, a2); a2 = fmaf(w2.y, cv[e + 2].y, a2);
            a2 = fmaf(w2.z, cv[e + 2].z, a2); a2 = fmaf(w2.w, cv[e + 2].w, a2);
            a3 = fmaf(w3.x, cv[e + 3].x, a3); a3 = fmaf(w3.y, cv[e + 3].y, a3);
            a3 = fmaf(w3.z, cv[e + 3].z, a3); a3 = fmaf(w3.w, cv[e + 3].w, a3);
        }
        Mb[(size_t)c * CH + dg] = (a0 + a1) + (a2 + a3);
    }
}

// ---------------- K4: pre = M_b @ q_sm + bias ; stats (round-5 structure) ----------------
__global__ void __launch_bounds__(256) k_proj(const float* __restrict__ Bias) {
    __shared__ unsigned As[128 * 36];
    __shared__ unsigned Bs[32 * 136];
    __shared__ float s1[8], s2[8];
    const int b   = blockIdx.y;
    const int n0  = blockIdx.x * 128;
    const int tid = threadIdx.x;
    const int lane = tid & 31;
    const int warp = tid >> 5;
    const int wm = warp >> 2, wn = warp & 3;
    const float* W  = g_M + (size_t)b * CH * CH;
    const float* Qb = g_qkv + (size_t)b * M3 * NPIX;

    float acc[4][4][4];
    #pragma unroll
    for (int mt = 0; mt < 4; mt++)
        #pragma unroll
        for (int nt = 0; nt < 4; nt++)
            #pragma unroll
            for (int r = 0; r < 4; r++) acc[mt][nt][r] = 0.f;

    for (int k0 = 0; k0 < CH; k0 += 32) {
        #pragma unroll
        for (int l = 0; l < 4; l++) {
            int t = tid + l * 256;
            int m = t >> 3, k4 = (t & 7) * 4;
            float4 v = *reinterpret_cast<const float4*>(&W[(size_t)m * CH + k0 + k4]);
            As[m * 36 + k4 + 0] = f2tf(v.x);
            As[m * 36 + k4 + 1] = f2tf(v.y);
            As[m * 36 + k4 + 2] = f2tf(v.z);
            As[m * 36 + k4 + 3] = f2tf(v.w);
        }
        #pragma unroll
        for (int l = 0; l < 4; l++) {
            int t = tid + l * 256;
            int k = t >> 5, n4 = (t & 31) * 4;
            float4 v = *reinterpret_cast<const float4*>(&Qb[(size_t)(k0 + k) * NPIX + n0 + n4]);
            Bs[k * 136 + n4 + 0] = f2tf(v.x);
            Bs[k * 136 + n4 + 1] = f2tf(v.y);
            Bs[k * 136 + n4 + 2] = f2tf(v.z);
            Bs[k * 136 + n4 + 3] = f2tf(v.w);
        }
        __syncthreads();
        #pragma unroll
        for (int kk = 0; kk < 32; kk += 8) {
            unsigned a[4][4], bf[4][2];
            #pragma unroll
            for (int mt = 0; mt < 4; mt++) {
                int r0 = wm * 64 + mt * 16 + (lane >> 2);
                int c0 = kk + (lane & 3);
                a[mt][0] = As[r0 * 36 + c0];
                a[mt][1] = As[(r0 + 8) * 36 + c0];
                a[mt][2] = As[r0 * 36 + c0 + 4];
                a[mt][3] = As[(r0 + 8) * 36 + c0 + 4];
            }
            #pragma unroll
            for (int nt = 0; nt < 4; nt++) {
                int cc = wn * 32 + nt * 8 + (lane >> 2);
                int rr = kk + (lane & 3);
                bf[nt][0] = Bs[rr * 136 + cc];
                bf[nt][1] = Bs[(rr + 4) * 136 + cc];
            }
            #pragma unroll
            for (int mt = 0; mt < 4; mt++)
                #pragma unroll
                for (int nt = 0; nt < 4; nt++)
                    mma_tf32(acc[mt][nt], a[mt], bf[nt]);
        }
        __syncthreads();
    }

    float* out = g_pre + (size_t)b * CH * NPIX;
    float lsum = 0.f, lsq = 0.f;
    #pragma unroll
    for (int mt = 0; mt < 4; mt++) {
        int row = wm * 64 + mt * 16 + (lane >> 2);
        float bias0 = __ldg(&Bias[row]);
        float bias1 = __ldg(&Bias[row + 8]);
        #pragma unroll
        for (int nt = 0; nt < 4; nt++) {
            int col = n0 + wn * 32 + nt * 8 + (lane & 3) * 2;
            float2 v0 = make_float2(acc[mt][nt][0] + bias0, acc[mt][nt][1] + bias0);
            float2 v1 = make_float2(acc[mt][nt][2] + bias1, acc[mt][nt][3] + bias1);
            lsum += v0.x + v0.y + v1.x + v1.y;
            lsq = fmaf(v0.x, v0.x, lsq); lsq = fmaf(v0.y, v0.y, lsq);
            lsq = fmaf(v1.x, v1.x, lsq); lsq = fmaf(v1.y, v1.y, lsq);
            *reinterpret_cast<float2*>(&out[(size_t)row * NPIX + col])       = v0;
            *reinterpret_cast<float2*>(&out[(size_t)(row + 8) * NPIX + col]) = v1;
        }
    }
    #pragma unroll
    for (int off = 16; off > 0; off >>= 1) {
        lsum += __shfl_down_sync(0xffffffffu, lsum, off);
        lsq  += __shfl_down_sync(0xffffffffu, lsq,  off);
    }
    if (lane == 0) { s1[warp] = lsum; s2[warp] = lsq; }
    __syncthreads();
    if (tid == 0) {
        float t1 = 0.f, t2 = 0.f;
        #pragma unroll
        for (int w = 0; w < 8; w++) { t1 += s1[w]; t2 += s2[w]; }
        atomicAdd(&g_stats[b * 2 + 0], t1);
        atomicAdd(&g_stats[b * 2 + 1], t2);
    }
}

// ---------------- K5: LayerNorm normalize + affine ----------------
__global__ void k_norm(const float* __restrict__ gnw, const float* __restrict__ gnb,
                       float* __restrict__ out) {
    size_t i4 = (size_t)blockIdx.x * 256 + threadIdx.x;
    size_t idx = i4 * 4;
    const float invCN = 1.f / (float)(CH * NPIX);
    int b = (int)(idx / ((size_t)CH * NPIX));
    int c = (int)((idx / NPIX) & (CH - 1));
    float mean = g_stats[b * 2 + 0] * invCN;
    float var  = g_stats[b * 2 + 1] * invCN - mean * mean;
    float rstd = rsqrtf(var + EPSV);
    float w  = gnw[c] * rstd;
    float bb = gnb[c] - mean * w;
    float4 v = *reinterpret_cast<const float4*>(g_pre + idx);
    v.x = fmaf(v.x, w, bb);
    v.y = fmaf(v.y, w, bb);
    v.z = fmaf(v.z, w, bb);
    v.w = fmaf(v.w, w, bb);
    *reinterpret_cast<float4*>(out + idx) = v;
}

// ---------------- launcher ----------------
extern "C" void kernel_launch(void* const* d_in, const int* in_sizes, int n_in,
                              void* d_out, int out_size) {
    const float* x     = (const float*)d_in[0];
    const float* w_qkv = (const float*)d_in[1];
    const float* w_out = (const float*)d_in[2];
    const float* b_out = (const float*)d_in[3];
    const float* gnw   = (const float*)d_in[4];
    const float* gnb   = (const float*)d_in[5];

    cudaFuncSetAttribute(k_gemm_fused, cudaFuncAttributeMaxDynamicSharedMemorySize, SMEM_GEMM);

    k_gemm_fused<<<dim3(32, 16), 256, SMEM_GEMM>>>(w_qkv, x);
    k_context<<<dim3(NCHUNK, 16), 256>>>();
    k_reduce2<<<dim3(4, NHEAD, BATCH), 256>>>();
    k_buildM2<<<dim3(16, BATCH), 256>>>(w_out);
    k_proj<<<dim3(32, 16), 256>>>(b_out);
    k_norm<<<8192, 256>>>(gnw, gnb, (float*)d_out);
}